// round 10
// baseline (speedup 1.0000x reference)
#include <cuda_runtime.h>
#include <math.h>
#include <stdint.h>

#define NM   8192
#define NCND 30
#define DD   300
#define WIN  100
#define TOPKK 25
#define NEGV (-1e10f)

#define CHUNK   100          // d-tile width (3 chunks of 100 = 300), even -> 50 f32x2 pairs
#define CSTR    102          // smem row stride: even (8B-aligned rows for LDS.64), 102%32=6 -> half-warp conflict-free
#define THREADS 128

// smem layout (floats)
#define OFF_T    0
#define OFF_E    (OFF_T + WIN * CSTR)            // 10200
#define OFF_B1   (OFF_E + 32 * CSTR)             // +3264
#define OFF_B2   (OFF_B1 + DD)
#define OFF_PART (OFF_B2 + DD)                   // 4*100
#define OFF_TS   (OFF_PART + 4 * WIN)
#define OFF_BVAL (OFF_TS + WIN)                  // 32
#define OFF_PROB (OFF_BVAL + 32)                 // 32
#define OFF_FCS  (OFF_PROB + 32)                 // 304
#define OFF_BIDX (OFF_FCS + 304)                 // 32 ints
#define SMEM_FLOATS (OFF_BIDX + 32)
#define SMEM_BYTES  (SMEM_FLOATS * 4)            // ~60 KB -> 3 CTAs/SM

// packed fp32x2 FMA (sm_100+): d = a*b + c on both 32-bit halves
#define FMA_F32X2(d_, a_, b_, c_) \
    asm("fma.rn.f32x2 %0, %1, %2, %3;" : "=l"(d_) : "l"(a_), "l"(b_), "l"(c_))

// ---------------- mask decoding (robust to bool-u8 / int32 / float32 encodings) ----------------
__device__ int g_mask_fmt;                 // 0 = u8, 1 = int32, 2 = float32
__device__ unsigned char g_mask[NM * WIN];

__global__ void detect_mask_fmt_kernel(const unsigned char* __restrict__ m) {
    __shared__ int nz_off;
    if (threadIdx.x == 0) nz_off = 0;
    __syncthreads();
    int local = 0;
    // Reading the first NM*WIN bytes is safe for all three candidate encodings.
    for (int i = threadIdx.x; i < NM * WIN; i += blockDim.x)
        if ((i & 3) != 0 && m[i] != 0) local++;
    atomicAdd(&nz_off, local);
    __syncthreads();
    if (threadIdx.x == 0) {
        int fmt;
        if (nz_off == 0)       fmt = 1;            // only byte-0 of each 4B word nonzero -> int32
        else if (m[0] != 0)    fmt = 0;            // bool stored as 1 byte (first token of row0 valid)
        else                   fmt = 2;            // float32 (1.0f has byte0 == 0)
        g_mask_fmt = fmt;
    }
}

__global__ void decode_mask_kernel(const void* __restrict__ m) {
    int i = blockIdx.x * blockDim.x + threadIdx.x;
    if (i >= NM * WIN) return;
    int fmt = g_mask_fmt;
    unsigned char v;
    if (fmt == 0)      v = (((const unsigned char*)m)[i] != 0);
    else if (fmt == 1) v = (((const int*)m)[i] != 0);
    else               v = (((const float*)m)[i] != 0.0f);
    g_mask[i] = v;
}

// ---------------- fused per-mention kernel (d-tiled, f32x2 GEMM, occupancy 3) ----------------
__global__ void __launch_bounds__(THREADS, 3)
fused_mention_kernel(const float* __restrict__ emb,     // (NM, NCND, DD)
                     const float* __restrict__ tok,     // (NM, WIN, DD)
                     const float* __restrict__ B1,      // (DD,)
                     const float* __restrict__ B2,      // (DD,)
                     float* __restrict__ out)           // (NM, NCND)
{
    extern __shared__ float sm[];
    float* Tsm  = sm + OFF_T;     // (WIN, CSTR) chunk of T
    float* Esc  = sm + OFF_E;     // (32, CSTR)  chunk of E * B_diag2
    float* B1s  = sm + OFF_B1;
    float* B2s  = sm + OFF_B2;
    float* part = sm + OFF_PART;
    float* ts   = sm + OFF_TS;
    float* bval = sm + OFF_BVAL;
    float* prob = sm + OFF_PROB;
    float* fcs  = sm + OFF_FCS;
    int*   bidx = (int*)(sm + OFF_BIDX);

    const int n   = blockIdx.x;
    const int tid = threadIdx.x;

    const float* Eg = emb + (size_t)n * NCND * DD;
    const float* Tg = tok + (size_t)n * WIN * DD;

    // ---- stage B1 / B2 ----
    for (int i = tid; i < DD; i += THREADS) { B1s[i] = B1[i]; B2s[i] = B2[i]; }
    __syncthreads();

    // ---- GEMM over 3 d-chunks: scores[c][w] = sum_d E[c,d]*B2[d]*T[w,d] ----
    const int tw = tid & 31;
    const int tc = tid >> 5;           // 0..3: candidate block of 8 (30 real + 2 pad)
    int row[4];
#pragma unroll
    for (int j = 0; j < 4; j++) {
        int w = tw + 32 * j;
        row[j] = (w < WIN) ? w : (w - WIN);   // clamp pad lanes (results discarded)
    }
    const float* tp0 = Tsm + row[0] * CSTR;
    const float* tp1 = Tsm + row[1] * CSTR;
    const float* tp2 = Tsm + row[2] * CSTR;
    const float* tp3 = Tsm + row[3] * CSTR;
    const float* ep  = Esc + (tc * 8) * CSTR;

    // packed accumulators: lane0 = even-d partial, lane1 = odd-d partial
    unsigned long long acc2[8][4];
#pragma unroll
    for (int i = 0; i < 8; i++)
#pragma unroll
        for (int j = 0; j < 4; j++) acc2[i][j] = 0ull;

    for (int ch = 0; ch < 3; ch++) {
        const int d0 = ch * CHUNK;
        // stage E chunk (B2-scaled) and T chunk into smem
        for (int idx = tid; idx < NCND * CHUNK; idx += THREADS) {
            int c = idx / CHUNK, d = idx - c * CHUNK;
            Esc[c * CSTR + d] = Eg[c * DD + d0 + d] * B2s[d0 + d];
        }
        for (int idx = tid; idx < WIN * CHUNK; idx += THREADS) {
            int r = idx / CHUNK, d = idx - r * CHUNK;
            Tsm[r * CSTR + d] = Tg[r * DD + d0 + d];
        }
        __syncthreads();

#pragma unroll 2
        for (int d = 0; d < CHUNK; d += 2) {
            // 8B-aligned: row*CSTR even, d even
            unsigned long long t0 = *(const unsigned long long*)(tp0 + d);
            unsigned long long t1 = *(const unsigned long long*)(tp1 + d);
            unsigned long long t2 = *(const unsigned long long*)(tp2 + d);
            unsigned long long t3 = *(const unsigned long long*)(tp3 + d);
#pragma unroll
            for (int i = 0; i < 8; i++) {
                unsigned long long e = *(const unsigned long long*)(ep + i * CSTR + d);
                FMA_F32X2(acc2[i][0], e, t0, acc2[i][0]);
                FMA_F32X2(acc2[i][1], e, t1, acc2[i][1]);
                FMA_F32X2(acc2[i][2], e, t2, acc2[i][2]);
                FMA_F32X2(acc2[i][3], e, t3, acc2[i][3]);
            }
        }
        __syncthreads();
    }

    // ---- horizontal add of packed halves -> scalar scores ----
    float acc[8][4];
#pragma unroll
    for (int i = 0; i < 8; i++)
#pragma unroll
        for (int j = 0; j < 4; j++) {
            float lo = __uint_as_float((unsigned)(acc2[i][j] & 0xffffffffull));
            float hi = __uint_as_float((unsigned)(acc2[i][j] >> 32));
            acc[i][j] = lo + hi;
        }

    // ---- per-thread max over its candidate slice (skip c>=30 padding) ----
    const int cvalid = (tc == 3) ? 6 : 8;    // tc==3 owns c=24..31; only 24..29 real
#pragma unroll
    for (int j = 0; j < 4; j++) {
        int w = tw + 32 * j;
        if (w < WIN) {
            float m = acc[0][j];
            for (int i = 1; i < cvalid; i++) m = fmaxf(m, acc[i][j]);
            part[tc * WIN + w] = m;
        }
    }
    __syncthreads();

    // ---- combine 4 partials, apply mask ----
    if (tid < WIN) {
        float m = part[tid];
        m = fmaxf(m, part[WIN + tid]);
        m = fmaxf(m, part[2 * WIN + tid]);
        m = fmaxf(m, part[3 * WIN + tid]);
        ts[tid] = g_mask[n * WIN + tid] ? m : NEGV;
    }
    __syncthreads();

    // ---- top-25 + softmax (warp 0) ----
    if (tid < 32) {
        for (int t = 0; t < TOPKK; t++) {
            float v = -INFINITY; int ix = WIN;
            for (int w = tid; w < WIN; w += 32) {
                float s = ts[w];
                if (s > v) { v = s; ix = w; }
            }
#pragma unroll
            for (int off = 16; off; off >>= 1) {
                float ov = __shfl_down_sync(0xffffffffu, v, off);
                int   oi = __shfl_down_sync(0xffffffffu, ix, off);
                if (ov > v || (ov == v && oi < ix)) { v = ov; ix = oi; }
            }
            v  = __shfl_sync(0xffffffffu, v, 0);
            ix = __shfl_sync(0xffffffffu, ix, 0);
            if (tid == 0) { bval[t] = v; bidx[t] = ix; ts[ix] = -INFINITY; }
            __syncwarp();
        }
        float bv = (tid < TOPKK) ? bval[tid] : -INFINITY;
        float vmax = __shfl_sync(0xffffffffu, bv, 0);   // bval[0] is the global max
        float e = (tid < TOPKK) ? expf(bv - vmax) : 0.0f;
        float s = e;
#pragma unroll
        for (int off = 16; off; off >>= 1) s += __shfl_down_sync(0xffffffffu, s, off);
        s = __shfl_sync(0xffffffffu, s, 0);
        if (tid < TOPKK) prob[tid] = e / s;
    }
    __syncthreads();

    // ---- fcs[d] = sum_t prob[t] * T[bidx[t]][d] (from gmem, L2-hot), scaled by B1 ----
    for (int d = tid; d < DD; d += THREADS) {
        float f = 0.0f;
#pragma unroll
        for (int t = 0; t < TOPKK; t++)
            f = fmaf(prob[t], Tg[bidx[t] * DD + d], f);
        fcs[d] = f * B1s[d];
    }
    __syncthreads();

    // ---- vals[c] = E[c,:] . fcs ----
    {
        const int wid = tid >> 5, lane = tid & 31;
        for (int c = wid; c < NCND; c += 4) {
            float s = 0.0f;
            for (int k = lane; k < DD; k += 32)
                s = fmaf(Eg[c * DD + k], fcs[k], s);
#pragma unroll
            for (int off = 16; off; off >>= 1) s += __shfl_down_sync(0xffffffffu, s, off);
            if (lane == 0) out[n * NCND + c] = s;
        }
    }
}

// ---------------- launch ----------------
extern "C" void kernel_launch(void* const* d_in, const int* in_sizes, int n_in,
                              void* d_out, int out_size) {
    const float* emb = nullptr;
    const float* tok = nullptr;
    const float* b1  = nullptr;
    const float* b2  = nullptr;
    const void*  msk = nullptr;

    for (int i = 0; i < n_in; i++) {
        int s = in_sizes[i];
        if (s == NM * NCND * DD)      emb = (const float*)d_in[i];
        else if (s == NM * WIN * DD)  tok = (const float*)d_in[i];
        else if (s == NM * WIN)       msk = d_in[i];
        else if (s == DD) {
            if (!b1) b1 = (const float*)d_in[i];   // B_diag1 comes first in input order
            else     b2 = (const float*)d_in[i];
        }
    }
    if (!emb || !tok || !msk || !b1 || !b2) return;

    cudaFuncSetAttribute(fused_mention_kernel,
                         cudaFuncAttributeMaxDynamicSharedMemorySize, SMEM_BYTES);

    detect_mask_fmt_kernel<<<1, 256>>>((const unsigned char*)msk);
    decode_mask_kernel<<<(NM * WIN + 255) / 256, 256>>>(msk);
    fused_mention_kernel<<<NM, THREADS, SMEM_BYTES>>>(emb, tok, b1, b2, (float*)d_out);
}

// round 11
// speedup vs baseline: 1.2806x; 1.2806x over previous
#include <cuda_runtime.h>
#include <math.h>
#include <stdint.h>

#define NM   8192
#define NCND 30
#define DD   300
#define WIN  100
#define TOPKK 25
#define NEGV (-1e10f)

#define CHUNK   100          // d-tile width (3 chunks of 100 = 300), even -> 50 f32x2 pairs
#define CSTR    102          // smem row stride: even (8B-aligned rows for LDS.64), 102%32=6 -> half-warp conflict-free
#define THREADS 128

// smem layout (floats)
#define OFF_T    0
#define OFF_E    (OFF_T + WIN * CSTR)            // 10200
#define OFF_B1   (OFF_E + 32 * CSTR)             // +3264
#define OFF_B2   (OFF_B1 + DD)
#define OFF_PART (OFF_B2 + DD)                   // 4*100
#define OFF_TS   (OFF_PART + 4 * WIN)
#define OFF_BVAL (OFF_TS + WIN)                  // 32
#define OFF_PROB (OFF_BVAL + 32)                 // 32
#define OFF_FCS  (OFF_PROB + 32)                 // 304
#define OFF_BIDX (OFF_FCS + 304)                 // 32 ints
#define SMEM_FLOATS (OFF_BIDX + 32)
#define SMEM_BYTES  (SMEM_FLOATS * 4)            // ~60 KB -> 3 CTAs/SM

// packed fp32x2 FMA (sm_100+): d = a*b + c on both 32-bit halves
#define FMA_F32X2(d_, a_, b_, c_) \
    asm("fma.rn.f32x2 %0, %1, %2, %3;" : "=l"(d_) : "l"(a_), "l"(b_), "l"(c_))

// ---------------- mask decoding (robust to bool-u8 / int32 / float32 encodings) ----------------
__device__ int g_mask_fmt;                 // 0 = u8, 1 = int32, 2 = float32
__device__ int g_nz_off;                   // count of nonzero bytes at offsets i%4 != 0
__device__ unsigned char g_mask[NM * WIN];

__global__ void reset_detect_kernel() {
    if (threadIdx.x == 0) g_nz_off = 0;
}

// Parallel scan of the first NM*WIN bytes (safe for all three candidate encodings).
__global__ void scan_mask_kernel(const unsigned char* __restrict__ m) {
    __shared__ int blk;
    if (threadIdx.x == 0) blk = 0;
    __syncthreads();
    int local = 0;
    int stride = gridDim.x * blockDim.x;
    for (int i = blockIdx.x * blockDim.x + threadIdx.x; i < NM * WIN; i += stride)
        if ((i & 3) != 0 && m[i] != 0) local++;
    if (local) atomicAdd(&blk, local);
    __syncthreads();
    if (threadIdx.x == 0 && blk) atomicAdd(&g_nz_off, blk);
}

__global__ void finalize_detect_kernel(const unsigned char* __restrict__ m) {
    if (threadIdx.x == 0) {
        int fmt;
        if (g_nz_off == 0)     fmt = 1;            // only byte-0 of each 4B word nonzero -> int32
        else if (m[0] != 0)    fmt = 0;            // bool stored as 1 byte (first token of row0 valid)
        else                   fmt = 2;            // float32 (1.0f has byte0 == 0)
        g_mask_fmt = fmt;
    }
}

__global__ void decode_mask_kernel(const void* __restrict__ m) {
    int i = blockIdx.x * blockDim.x + threadIdx.x;
    if (i >= NM * WIN) return;
    int fmt = g_mask_fmt;
    unsigned char v;
    if (fmt == 0)      v = (((const unsigned char*)m)[i] != 0);
    else if (fmt == 1) v = (((const int*)m)[i] != 0);
    else               v = (((const float*)m)[i] != 0.0f);
    g_mask[i] = v;
}

// ---------------- fused per-mention kernel (d-tiled, f32x2 GEMM, occupancy 3) ----------------
__global__ void __launch_bounds__(THREADS, 3)
fused_mention_kernel(const float* __restrict__ emb,     // (NM, NCND, DD)
                     const float* __restrict__ tok,     // (NM, WIN, DD)
                     const float* __restrict__ B1,      // (DD,)
                     const float* __restrict__ B2,      // (DD,)
                     float* __restrict__ out)           // (NM, NCND)
{
    extern __shared__ float sm[];
    float* Tsm  = sm + OFF_T;     // (WIN, CSTR) chunk of T
    float* Esc  = sm + OFF_E;     // (32, CSTR)  chunk of E * B_diag2
    float* B1s  = sm + OFF_B1;
    float* B2s  = sm + OFF_B2;
    float* part = sm + OFF_PART;
    float* ts   = sm + OFF_TS;
    float* bval = sm + OFF_BVAL;
    float* prob = sm + OFF_PROB;
    float* fcs  = sm + OFF_FCS;
    int*   bidx = (int*)(sm + OFF_BIDX);

    const int n   = blockIdx.x;
    const int tid = threadIdx.x;

    const float* Eg = emb + (size_t)n * NCND * DD;
    const float* Tg = tok + (size_t)n * WIN * DD;

    // ---- stage B1 / B2 ----
    for (int i = tid; i < DD; i += THREADS) { B1s[i] = B1[i]; B2s[i] = B2[i]; }
    __syncthreads();

    // ---- GEMM over 3 d-chunks: scores[c][w] = sum_d E[c,d]*B2[d]*T[w,d] ----
    const int tw = tid & 31;
    const int tc = tid >> 5;           // 0..3: candidate block of 8 (30 real + 2 pad)
    int row[4];
#pragma unroll
    for (int j = 0; j < 4; j++) {
        int w = tw + 32 * j;
        row[j] = (w < WIN) ? w : (w - WIN);   // clamp pad lanes (results discarded)
    }
    const float* tp0 = Tsm + row[0] * CSTR;
    const float* tp1 = Tsm + row[1] * CSTR;
    const float* tp2 = Tsm + row[2] * CSTR;
    const float* tp3 = Tsm + row[3] * CSTR;
    const float* ep  = Esc + (tc * 8) * CSTR;

    // packed accumulators: lane0 = even-d partial, lane1 = odd-d partial
    unsigned long long acc2[8][4];
#pragma unroll
    for (int i = 0; i < 8; i++)
#pragma unroll
        for (int j = 0; j < 4; j++) acc2[i][j] = 0ull;

    for (int ch = 0; ch < 3; ch++) {
        const int d0 = ch * CHUNK;
        // stage E chunk (B2-scaled) and T chunk into smem
        for (int idx = tid; idx < NCND * CHUNK; idx += THREADS) {
            int c = idx / CHUNK, d = idx - c * CHUNK;
            Esc[c * CSTR + d] = Eg[c * DD + d0 + d] * B2s[d0 + d];
        }
        for (int idx = tid; idx < WIN * CHUNK; idx += THREADS) {
            int r = idx / CHUNK, d = idx - r * CHUNK;
            Tsm[r * CSTR + d] = Tg[r * DD + d0 + d];
        }
        __syncthreads();

#pragma unroll 2
        for (int d = 0; d < CHUNK; d += 2) {
            // 8B-aligned: row*CSTR even, d even
            unsigned long long t0 = *(const unsigned long long*)(tp0 + d);
            unsigned long long t1 = *(const unsigned long long*)(tp1 + d);
            unsigned long long t2 = *(const unsigned long long*)(tp2 + d);
            unsigned long long t3 = *(const unsigned long long*)(tp3 + d);
#pragma unroll
            for (int i = 0; i < 8; i++) {
                unsigned long long e = *(const unsigned long long*)(ep + i * CSTR + d);
                FMA_F32X2(acc2[i][0], e, t0, acc2[i][0]);
                FMA_F32X2(acc2[i][1], e, t1, acc2[i][1]);
                FMA_F32X2(acc2[i][2], e, t2, acc2[i][2]);
                FMA_F32X2(acc2[i][3], e, t3, acc2[i][3]);
            }
        }
        __syncthreads();
    }

    // ---- horizontal add of packed halves -> scalar scores ----
    float acc[8][4];
#pragma unroll
    for (int i = 0; i < 8; i++)
#pragma unroll
        for (int j = 0; j < 4; j++) {
            float lo = __uint_as_float((unsigned)(acc2[i][j] & 0xffffffffull));
            float hi = __uint_as_float((unsigned)(acc2[i][j] >> 32));
            acc[i][j] = lo + hi;
        }

    // ---- per-thread max over its candidate slice (skip c>=30 padding) ----
    const int cvalid = (tc == 3) ? 6 : 8;    // tc==3 owns c=24..31; only 24..29 real
#pragma unroll
    for (int j = 0; j < 4; j++) {
        int w = tw + 32 * j;
        if (w < WIN) {
            float m = acc[0][j];
            for (int i = 1; i < cvalid; i++) m = fmaxf(m, acc[i][j]);
            part[tc * WIN + w] = m;
        }
    }
    __syncthreads();

    // ---- combine 4 partials, apply mask ----
    if (tid < WIN) {
        float m = part[tid];
        m = fmaxf(m, part[WIN + tid]);
        m = fmaxf(m, part[2 * WIN + tid]);
        m = fmaxf(m, part[3 * WIN + tid]);
        ts[tid] = g_mask[n * WIN + tid] ? m : NEGV;
    }
    __syncthreads();

    // ---- top-25 + softmax (warp 0) ----
    if (tid < 32) {
        for (int t = 0; t < TOPKK; t++) {
            float v = -INFINITY; int ix = WIN;
            for (int w = tid; w < WIN; w += 32) {
                float s = ts[w];
                if (s > v) { v = s; ix = w; }
            }
#pragma unroll
            for (int off = 16; off; off >>= 1) {
                float ov = __shfl_down_sync(0xffffffffu, v, off);
                int   oi = __shfl_down_sync(0xffffffffu, ix, off);
                if (ov > v || (ov == v && oi < ix)) { v = ov; ix = oi; }
            }
            v  = __shfl_sync(0xffffffffu, v, 0);
            ix = __shfl_sync(0xffffffffu, ix, 0);
            if (tid == 0) { bval[t] = v; bidx[t] = ix; ts[ix] = -INFINITY; }
            __syncwarp();
        }
        float bv = (tid < TOPKK) ? bval[tid] : -INFINITY;
        float vmax = __shfl_sync(0xffffffffu, bv, 0);   // bval[0] is the global max
        float e = (tid < TOPKK) ? expf(bv - vmax) : 0.0f;
        float s = e;
#pragma unroll
        for (int off = 16; off; off >>= 1) s += __shfl_down_sync(0xffffffffu, s, off);
        s = __shfl_sync(0xffffffffu, s, 0);
        if (tid < TOPKK) prob[tid] = e / s;
    }
    __syncthreads();

    // ---- fcs[d] = sum_t prob[t] * T[bidx[t]][d] (from gmem, L2-hot), scaled by B1 ----
    for (int d = tid; d < DD; d += THREADS) {
        float f = 0.0f;
#pragma unroll
        for (int t = 0; t < TOPKK; t++)
            f = fmaf(prob[t], Tg[bidx[t] * DD + d], f);
        fcs[d] = f * B1s[d];
    }
    __syncthreads();

    // ---- vals[c] = E[c,:] . fcs ----
    {
        const int wid = tid >> 5, lane = tid & 31;
        for (int c = wid; c < NCND; c += 4) {
            float s = 0.0f;
            for (int k = lane; k < DD; k += 32)
                s = fmaf(Eg[c * DD + k], fcs[k], s);
#pragma unroll
            for (int off = 16; off; off >>= 1) s += __shfl_down_sync(0xffffffffu, s, off);
            if (lane == 0) out[n * NCND + c] = s;
        }
    }
}

// ---------------- launch ----------------
extern "C" void kernel_launch(void* const* d_in, const int* in_sizes, int n_in,
                              void* d_out, int out_size) {
    const float* emb = nullptr;
    const float* tok = nullptr;
    const float* b1  = nullptr;
    const float* b2  = nullptr;
    const void*  msk = nullptr;

    for (int i = 0; i < n_in; i++) {
        int s = in_sizes[i];
        if (s == NM * NCND * DD)      emb = (const float*)d_in[i];
        else if (s == NM * WIN * DD)  tok = (const float*)d_in[i];
        else if (s == NM * WIN)       msk = d_in[i];
        else if (s == DD) {
            if (!b1) b1 = (const float*)d_in[i];   // B_diag1 comes first in input order
            else     b2 = (const float*)d_in[i];
        }
    }
    if (!emb || !tok || !msk || !b1 || !b2) return;

    cudaFuncSetAttribute(fused_mention_kernel,
                         cudaFuncAttributeMaxDynamicSharedMemorySize, SMEM_BYTES);

    reset_detect_kernel<<<1, 32>>>();
    scan_mask_kernel<<<256, 256>>>((const unsigned char*)msk);
    finalize_detect_kernel<<<1, 32>>>((const unsigned char*)msk);
    decode_mask_kernel<<<(NM * WIN + 255) / 256, 256>>>(msk);
    fused_mention_kernel<<<NM, THREADS, SMEM_BYTES>>>(emb, tok, b1, b2, (float*)d_out);
}